// round 16
// baseline (speedup 1.0000x reference)
#include <cuda_runtime.h>
#include <cuda_fp16.h>
#include <math.h>
#include <stdint.h>

// ---------------- Problem constants ----------------
#define BSZ 2
#define SEQ 2048
#define DMODEL 2048
#define NH 16
#define KV_RANK 512
#define Q_RANK 1536
#define NOPE 128
#define ROPE_D 64
#define VDIM 128
#define QKD 192           // NOPE + ROPE_D
#define MTOT (BSZ*SEQ)    // 4096
#define SCALE 0.07216878364870323f   // 192^-0.5

// ---------------- fp32 scratch ----------------
__device__ float g_kr  [MTOT * ROPE_D];
__device__ float g_qr  [MTOT * NH * ROPE_D];
__device__ float g_cos [SEQ * (ROPE_D/2)];
__device__ float g_sin [SEQ * (ROPE_D/2)];

// ---------------- fp16 scratch: A-side = hi+lo, B-side = hi only ----------------
__device__ __half g_x_hi  [MTOT*DMODEL],    g_x_lo  [MTOT*DMODEL];
__device__ __half g_cq_hi [MTOT*Q_RANK],    g_cq_lo [MTOT*Q_RANK];
__device__ __half g_ckv_hi[MTOT*KV_RANK],   g_ckv_lo[MTOT*KV_RANK];
__device__ __half g_at_hi [MTOT*NH*VDIM],   g_at_lo [MTOT*NH*VDIM];
__device__ __half g_Qhi   [BSZ*NH*SEQ*QKD], g_Qlo   [BSZ*NH*SEQ*QKD];
__device__ __half g_vchi  [MTOT*NH*VDIM];                       // B-side: hi only
__device__ __half g_Khi   [BSZ*NH*SEQ*QKD];                     // B-side: hi only
__device__ __half g_wqd  [Q_RANK*DMODEL];
__device__ __half g_wqu  [NH*NOPE*Q_RANK];
__device__ __half g_wqr  [NH*ROPE_D*Q_RANK];
__device__ __half g_wkvd [KV_RANK*DMODEL];
__device__ __half g_wku  [NH*NOPE*KV_RANK];
__device__ __half g_wvu  [NH*VDIM*KV_RANK];
__device__ __half g_wkr  [ROPE_D*DMODEL];
__device__ __half g_wo   [DMODEL*NH*VDIM];

// ---------------- helpers ----------------
__device__ __forceinline__ uint32_t smem_u32(const void* p) {
    uint32_t a;
    asm("{ .reg .u64 t; cvta.to.shared.u64 t, %1; cvt.u32.u64 %0, t; }" : "=r"(a) : "l"(p));
    return a;
}
__device__ __forceinline__ void cp16(uint32_t dst, const void* src) {
    asm volatile("cp.async.cg.shared.global [%0], [%1], 16;" :: "r"(dst), "l"(src));
}
__device__ __forceinline__ void ldm4(uint32_t (&r)[4], uint32_t a) {
    asm volatile("ldmatrix.sync.aligned.m8n8.x4.shared.b16 {%0,%1,%2,%3}, [%4];"
                 : "=r"(r[0]), "=r"(r[1]), "=r"(r[2]), "=r"(r[3]) : "r"(a));
}
__device__ __forceinline__ void ldm4t(uint32_t (&r)[4], uint32_t a) {
    asm volatile("ldmatrix.sync.aligned.m8n8.x4.trans.shared.b16 {%0,%1,%2,%3}, [%4];"
                 : "=r"(r[0]), "=r"(r[1]), "=r"(r[2]), "=r"(r[3]) : "r"(a));
}
__device__ __forceinline__ void mma_f16(float (&c)[4], const uint32_t (&a)[4], const uint32_t (&b)[2]) {
    asm volatile("mma.sync.aligned.m16n8k16.row.col.f32.f16.f16.f32 "
                 "{%0,%1,%2,%3}, {%4,%5,%6,%7}, {%8,%9}, {%0,%1,%2,%3};"
                 : "+f"(c[0]), "+f"(c[1]), "+f"(c[2]), "+f"(c[3])
                 : "r"(a[0]), "r"(a[1]), "r"(a[2]), "r"(a[3]), "r"(b[0]), "r"(b[1]));
}
__device__ __forceinline__ void store_hilo(__half* Hi, __half* Lo, size_t off, float a, float b) {
    __half h0 = __float2half_rn(a), h1 = __float2half_rn(b);
    *(__half2*)(Hi + off) = __halves2half2(h0, h1);
    *(__half2*)(Lo + off) = __halves2half2(__float2half_rn(a - __half2float(h0)),
                                           __float2half_rn(b - __half2float(h1)));
}
__device__ __forceinline__ void store_hi(__half* Hi, size_t off, float a, float b) {
    *(__half2*)(Hi + off) = __halves2half2(__float2half_rn(a), __float2half_rn(b));
}

// ---------------- splits ----------------
__global__ void split2_kernel(const float4* __restrict__ src,
                              __half2* __restrict__ hi, __half2* __restrict__ lo, int n4)
{
    int i = blockIdx.x * blockDim.x + threadIdx.x;
    if (i >= n4) return;
    float4 v = src[i];
    __half h0 = __float2half_rn(v.x), h1 = __float2half_rn(v.y);
    __half h2 = __float2half_rn(v.z), h3 = __float2half_rn(v.w);
    hi[2*i]   = __halves2half2(h0, h1);
    hi[2*i+1] = __halves2half2(h2, h3);
    lo[2*i]   = __halves2half2(__float2half_rn(v.x - __half2float(h0)),
                               __float2half_rn(v.y - __half2float(h1)));
    lo[2*i+1] = __halves2half2(__float2half_rn(v.z - __half2float(h2)),
                               __float2half_rn(v.w - __half2float(h3)));
}
__global__ void split1_kernel(const float4* __restrict__ src, __half2* __restrict__ hi, int n4)
{
    int i = blockIdx.x * blockDim.x + threadIdx.x;
    if (i >= n4) return;
    float4 v = src[i];
    hi[2*i]   = __halves2half2(__float2half_rn(v.x), __float2half_rn(v.y));
    hi[2*i+1] = __halves2half2(__float2half_rn(v.z), __float2half_rn(v.w));
}

// ---------------- mma.sync fp16x2 GEMM: C[M,N] = A[M,K] * B[N,K]^T ----------------
// A = Ahi + Alo (exact), B = Bhi (fp16-rounded). 2 mma passes per tile.
template<int TILE_N, int EPI>
__global__ void __launch_bounds__(256) gemm_f16x2(
    const __half* __restrict__ Ahi, const __half* __restrict__ Alo,
    const __half* __restrict__ Bhi,
    float* __restrict__ C,
    __half* __restrict__ Chi, __half* __restrict__ Clo,
    int M, int N, int K, float scl)
{
    constexpr int BK = 32;
    constexpr int ASTR = 40;
    constexpr int ABYTES = 128 * ASTR * 2;
    constexpr int BBYTES = TILE_N * ASTR * 2;
    constexpr int STAGE  = 2 * ABYTES + BBYTES;
    constexpr int WN = TILE_N / 4;
    constexpr int NT = WN / 8;

    extern __shared__ char sm_raw[];
    const uint32_t s0 = smem_u32(sm_raw);

    const int tid  = threadIdx.x;
    const int lane = tid & 31;
    const int warp = tid >> 5;
    const int wm0  = (warp & 1) * 64;
    const int wn0  = (warp >> 1) * WN;
    const int mBase = blockIdx.y * 128;
    const int nBase = blockIdx.x * TILE_N;

    float acc[4][NT][4];
#pragma unroll
    for (int i = 0; i < 4; i++)
#pragma unroll
        for (int j = 0; j < NT; j++)
#pragma unroll
            for (int q = 0; q < 4; q++) acc[i][j][q] = 0.0f;

    auto load = [&](int c, int s) {
        uint32_t base = s0 + s * STAGE;
        int k0 = c * BK;
#pragma unroll
        for (int i = 0; i < 2; i++) {
            int idx = tid + i * 256;
            int row = idx >> 2, c4 = idx & 3;
            uint32_t d = base + row * (ASTR * 2) + c4 * 16;
            const size_t goff = (size_t)(mBase + row) * K + k0 + c4 * 8;
            cp16(d,           Ahi + goff);
            cp16(d + ABYTES,  Alo + goff);
        }
#pragma unroll
        for (int i = 0; i < TILE_N / 64; i++) {
            int idx = tid + i * 256;
            int row = idx >> 2, c4 = idx & 3;
            uint32_t d = base + 2 * ABYTES + row * (ASTR * 2) + c4 * 16;
            const size_t goff = (size_t)(nBase + row) * K + k0 + c4 * 8;
            cp16(d, Bhi + goff);
        }
        asm volatile("cp.async.commit_group;" ::: "memory");
    };

    const int nch = K / BK;
    load(0, 0);

    for (int c = 0; c < nch; c++) {
        const int s = c & 1;
        if (c + 1 < nch) {
            load(c + 1, s ^ 1);
            asm volatile("cp.async.wait_group 1;" ::: "memory");
        } else {
            asm volatile("cp.async.wait_group 0;" ::: "memory");
        }
        __syncthreads();

        const uint32_t aB = s0 + s * STAGE;
        const uint32_t bB = aB + 2 * ABYTES;
#pragma unroll
        for (int ks = 0; ks < 2; ks++) {
            uint32_t aH[4][4], aL[4][4];
#pragma unroll
            for (int i = 0; i < 4; i++) {
                int row = wm0 + i * 16 + (lane & 15);
                int kc  = ks * 16 + (lane >> 4) * 8;
                uint32_t ad = aB + row * (ASTR * 2) + kc * 2;
                ldm4(aH[i], ad);
                ldm4(aL[i], ad + ABYTES);
            }
            uint32_t bF[NT][2];
#pragma unroll
            for (int j2 = 0; j2 < NT / 2; j2++) {
                int nrow = wn0 + j2 * 16 + ((lane >> 4) << 3) + (lane & 7);
                int kc   = ks * 16 + ((lane >> 3) & 1) * 8;
                uint32_t bd = bB + nrow * (ASTR * 2) + kc * 2;
                uint32_t r[4];
                ldm4(r, bd);
                bF[2*j2][0] = r[0]; bF[2*j2][1] = r[1];
                bF[2*j2+1][0] = r[2]; bF[2*j2+1][1] = r[3];
            }
#pragma unroll
            for (int i = 0; i < 4; i++)
#pragma unroll
                for (int j = 0; j < NT; j++) {
                    mma_f16(acc[i][j], aH[i], bF[j]);
                    mma_f16(acc[i][j], aL[i], bF[j]);
                }
        }
        __syncthreads();
    }

#pragma unroll
    for (int i = 0; i < 4; i++)
#pragma unroll
        for (int j = 0; j < NT; j++) {
            int row = mBase + wm0 + i * 16 + (lane >> 2);
            int col = nBase + wn0 + j * 8 + (lane & 3) * 2;
            if (EPI == 0) {
                *(float2*)(C + (size_t)row * N + col)       = make_float2(acc[i][j][0], acc[i][j][1]);
                *(float2*)(C + (size_t)(row + 8) * N + col) = make_float2(acc[i][j][2], acc[i][j][3]);
            } else if (EPI == 1) {
                store_hilo(Chi, Clo, (size_t)row * N + col,       acc[i][j][0], acc[i][j][1]);
                store_hilo(Chi, Clo, (size_t)(row + 8) * N + col, acc[i][j][2], acc[i][j][3]);
            } else if (EPI == 3) {
                store_hi(Chi, (size_t)row * N + col,       acc[i][j][0], acc[i][j][1]);
                store_hi(Chi, (size_t)(row + 8) * N + col, acc[i][j][2], acc[i][j][3]);
            } else {
                int bb = row >> 11, ss = row & (SEQ - 1);
                int hh = col >> 7,  dd = col & 127;
                size_t o1 = (((size_t)(bb * NH + hh)) * SEQ + ss) * QKD + dd;
                if (EPI == 2) {
                    store_hilo(Chi, Clo, o1,           acc[i][j][0] * scl, acc[i][j][1] * scl);
                    store_hilo(Chi, Clo, o1 + 8 * QKD, acc[i][j][2] * scl, acc[i][j][3] * scl);
                } else {   // EPI == 4
                    store_hi(Chi, o1,           acc[i][j][0], acc[i][j][1]);
                    store_hi(Chi, o1 + 8 * QKD, acc[i][j][2], acc[i][j][3]);
                }
            }
        }
}

// ---------------- RoPE cos/sin table ----------------
__global__ void rope_table_kernel(const int* __restrict__ positions)
{
    int idx = blockIdx.x * blockDim.x + threadIdx.x;
    if (idx >= SEQ * (ROPE_D/2)) return;
    int s = idx / (ROPE_D/2);
    int i = idx % (ROPE_D/2);
    float pos = (float)positions[s];
    float inv = expf(-logf(10000.0f) * (float)i / (float)(ROPE_D/2));
    float ang = pos * inv;
    g_cos[idx] = cosf(ang);
    g_sin[idx] = sinf(ang);
}

// ---------------- Pack Q rope dims -> [b,h,s,128+d] hi/lo ----------------
__global__ void pack_q_rope_kernel()
{
    int idx = blockIdx.x * blockDim.x + threadIdx.x;
    const int total = BSZ * NH * SEQ * ROPE_D;
    if (idx >= total) return;
    int d = idx & (ROPE_D - 1);
    int s = (idx >> 6) & (SEQ - 1);
    int h = (idx >> 17) & (NH - 1);
    int b = idx >> 21;
    int row = b * SEQ + s;
    int i = d & 31;
    float c = g_cos[s * 32 + i];
    float sn = g_sin[s * 32 + i];
    float t1 = g_qr[(size_t)row * (NH * ROPE_D) + h * ROPE_D + i];
    float t2 = g_qr[(size_t)row * (NH * ROPE_D) + h * ROPE_D + i + 32];
    float val = ((d < 32) ? (t1 * c - t2 * sn) : (t2 * c + t1 * sn)) * SCALE;
    size_t o = (((size_t)(b * NH + h)) * SEQ + s) * QKD + NOPE + d;
    __half hh = __float2half_rn(val);
    g_Qhi[o] = hh;
    g_Qlo[o] = __float2half_rn(val - __half2float(hh));
}

// ---------------- Pack K rope dims (shared head) -> hi only ----------------
__global__ void pack_k_rope_kernel()
{
    int idx = blockIdx.x * blockDim.x + threadIdx.x;
    const int total = BSZ * NH * SEQ * ROPE_D;
    if (idx >= total) return;
    int d = idx & (ROPE_D - 1);
    int s = (idx >> 6) & (SEQ - 1);
    int h = (idx >> 17) & (NH - 1);
    int b = idx >> 21;
    int row = b * SEQ + s;
    int i = d & 31;
    float c = g_cos[s * 32 + i];
    float sn = g_sin[s * 32 + i];
    float t1 = g_kr[(size_t)row * ROPE_D + i];
    float t2 = g_kr[(size_t)row * ROPE_D + i + 32];
    float val = (d < 32) ? (t1 * c - t2 * sn) : (t2 * c + t1 * sn);
    size_t o = (((size_t)(b * NH + h)) * SEQ + s) * QKD + NOPE + d;
    g_Khi[o] = __float2half_rn(val);
}

// ---------------- Flash attention (mma.sync fp16x2, causal, BQ=128, 256 thr) ----------------
// smem: Qhi 128x400, Qlo 128x400, Khi 64x400, Vhi 64x272, Phi 128x144, Plo 128x144
#define QHI_OFF 0
#define QLO_OFF 51200
#define KHI_OFF 102400
#define VHI_OFF 128000
#define PHI_OFF 145408
#define PLO_OFF 163840
#define FLASH2_SMEM 182272

__global__ void __launch_bounds__(256) flash_mma_kernel()
{
    extern __shared__ char smc[];
    const uint32_t s0 = smem_u32(smc);
    const int tid = threadIdx.x, lane = tid & 31, w = tid >> 5;   // w = 0..7
    const int qt = gridDim.x - 1 - blockIdx.x;   // big tiles first
    const int h = blockIdx.y, b = blockIdx.z;
    const int qbase = qt * 128;
    const size_t qkB = ((size_t)(b * NH + h) * SEQ) * QKD;
    const int r1 = lane >> 2;
    const int cq0 = (lane & 3) * 2;

    // load Q hi/lo (128 x 192), row stride 400B
#pragma unroll
    for (int i = 0; i < 12; i++) {
        int idx = tid + i * 256;
        int row = idx / 24, c8 = idx % 24;
        size_t g = qkB + (size_t)(qbase + row) * QKD + c8 * 8;
        *(uint4*)(smc + QHI_OFF + row * 400 + c8 * 16) = *(const uint4*)(g_Qhi + g);
        *(uint4*)(smc + QLO_OFF + row * 400 + c8 * 16) = *(const uint4*)(g_Qlo + g);
    }

    float oacc[16][4];
#pragma unroll
    for (int n = 0; n < 16; n++)
#pragma unroll
        for (int q = 0; q < 4; q++) oacc[n][q] = 0.0f;
    float m1 = -INFINITY, m2 = -INFINITY, l1 = 0.0f, l2 = 0.0f;

    const int nkt = qbase / 64 + 2;   // k-tiles covering [0, qbase+128)
    for (int kt = 0; kt < nkt; kt++) {
        const int kbase = kt * 64;
        __syncthreads();
        // K tile (64 x 192)
#pragma unroll
        for (int i = 0; i < 6; i++) {
            int idx = tid + i * 256;
            int row = idx / 24, c8 = idx % 24;
            size_t g = qkB + (size_t)(kbase + row) * QKD + c8 * 8;
            *(uint4*)(smc + KHI_OFF + row * 400 + c8 * 16) = *(const uint4*)(g_Khi + g);
        }
        // V tile (64 x 128)
#pragma unroll
        for (int i = 0; i < 4; i++) {
            int idx = tid + i * 256;
            int row = idx / 16, c8 = idx % 16;
            size_t g = (size_t)(b * SEQ + kbase + row) * (NH * VDIM) + h * VDIM + c8 * 8;
            *(uint4*)(smc + VHI_OFF + row * 272 + c8 * 16) = *(const uint4*)(g_vchi + g);
        }
        __syncthreads();

        float sacc[8][4];
#pragma unroll
        for (int j = 0; j < 8; j++)
#pragma unroll
            for (int q = 0; q < 4; q++) sacc[j][q] = 0.0f;

#pragma unroll
        for (int ks = 0; ks < 12; ks++) {
            uint32_t aH[4], aL[4];
            uint32_t aaddr = s0 + QHI_OFF + (w * 16 + (lane & 15)) * 400
                           + (ks * 16 + (lane >> 4) * 8) * 2;
            ldm4(aH, aaddr);
            ldm4(aL, aaddr + 51200);
#pragma unroll
            for (int j2 = 0; j2 < 4; j2++) {
                uint32_t baddr = s0 + KHI_OFF
                               + (j2 * 16 + ((lane >> 4) << 3) + (lane & 7)) * 400
                               + (ks * 16 + ((lane >> 3) & 1) * 8) * 2;
                uint32_t r[4];
                ldm4(r, baddr);
                uint32_t b0[2] = {r[0], r[1]}, b1[2] = {r[2], r[3]};
                mma_f16(sacc[2*j2],   aH, b0);
                mma_f16(sacc[2*j2],   aL, b0);
                mma_f16(sacc[2*j2+1], aH, b1);
                mma_f16(sacc[2*j2+1], aL, b1);
            }
        }

        // causal mask (only when this k tile can exceed this warp's rows)
        if (kbase + 63 > qbase + w * 16) {
            int q1 = qbase + w * 16 + r1;
#pragma unroll
            for (int j = 0; j < 8; j++) {
                int kv = kbase + j * 8 + cq0;
                if (kv     > q1)     sacc[j][0] = -1e30f;
                if (kv + 1 > q1)     sacc[j][1] = -1e30f;
                if (kv     > q1 + 8) sacc[j][2] = -1e30f;
                if (kv + 1 > q1 + 8) sacc[j][3] = -1e30f;
            }
        }

        float mx1 = -1e30f, mx2 = -1e30f;
#pragma unroll
        for (int j = 0; j < 8; j++) {
            mx1 = fmaxf(mx1, fmaxf(sacc[j][0], sacc[j][1]));
            mx2 = fmaxf(mx2, fmaxf(sacc[j][2], sacc[j][3]));
        }
        mx1 = fmaxf(mx1, __shfl_xor_sync(0xFFFFFFFFu, mx1, 1));
        mx1 = fmaxf(mx1, __shfl_xor_sync(0xFFFFFFFFu, mx1, 2));
        mx2 = fmaxf(mx2, __shfl_xor_sync(0xFFFFFFFFu, mx2, 1));
        mx2 = fmaxf(mx2, __shfl_xor_sync(0xFFFFFFFFu, mx2, 2));
        float mn1 = fmaxf(m1, mx1), mn2 = fmaxf(m2, mx2);
        float a1 = expf(m1 - mn1), a2 = expf(m2 - mn2);
        float su1 = 0.0f, su2 = 0.0f;
#pragma unroll
        for (int j = 0; j < 8; j++) {
            sacc[j][0] = expf(sacc[j][0] - mn1);
            sacc[j][1] = expf(sacc[j][1] - mn1);
            sacc[j][2] = expf(sacc[j][2] - mn2);
            sacc[j][3] = expf(sacc[j][3] - mn2);
            su1 += sacc[j][0] + sacc[j][1];
            su2 += sacc[j][2] + sacc[j][3];
        }
        su1 += __shfl_xor_sync(0xFFFFFFFFu, su1, 1);
        su1 += __shfl_xor_sync(0xFFFFFFFFu, su1, 2);
        su2 += __shfl_xor_sync(0xFFFFFFFFu, su2, 1);
        su2 += __shfl_xor_sync(0xFFFFFFFFu, su2, 2);
        m1 = mn1; m2 = mn2;
        l1 = l1 * a1 + su1;
        l2 = l2 * a2 + su2;

        // P hi/lo to smem (stride 144B)
#pragma unroll
        for (int j = 0; j < 8; j++) {
            float p0 = sacc[j][0], p1 = sacc[j][1];
            __half h0 = __float2half_rn(p0), h1 = __float2half_rn(p1);
            int off = (w * 16 + r1) * 144 + (j * 8 + cq0) * 2;
            *(__half2*)(smc + PHI_OFF + off) = __halves2half2(h0, h1);
            *(__half2*)(smc + PLO_OFF + off) =
                __halves2half2(__float2half_rn(p0 - __half2float(h0)),
                               __float2half_rn(p1 - __half2float(h1)));
            float p2 = sacc[j][2], p3 = sacc[j][3];
            __half h2 = __float2half_rn(p2), h3 = __float2half_rn(p3);
            int off2 = (w * 16 + r1 + 8) * 144 + (j * 8 + cq0) * 2;
            *(__half2*)(smc + PHI_OFF + off2) = __halves2half2(h2, h3);
            *(__half2*)(smc + PLO_OFF + off2) =
                __halves2half2(__float2half_rn(p2 - __half2float(h2)),
                               __float2half_rn(p3 - __half2float(h3)));
        }
        __syncwarp();

#pragma unroll
        for (int n = 0; n < 16; n++) {
            oacc[n][0] *= a1; oacc[n][1] *= a1;
            oacc[n][2] *= a2; oacc[n][3] *= a2;
        }

#pragma unroll
        for (int ks = 0; ks < 4; ks++) {
            uint32_t pH[4], pL[4];
            uint32_t paddr = s0 + PHI_OFF + (w * 16 + (lane & 15)) * 144
                           + (ks * 16 + (lane >> 4) * 8) * 2;
            ldm4(pH, paddr);
            ldm4(pL, paddr + 18432);
#pragma unroll
            for (int n2 = 0; n2 < 8; n2++) {
                uint32_t vaddr = s0 + VHI_OFF + (ks * 16 + (lane & 15)) * 272
                               + (n2 * 16 + ((lane >> 4) << 3)) * 2;
                uint32_t r[4];
                ldm4t(r, vaddr);
                uint32_t b0[2] = {r[0], r[1]}, b1[2] = {r[2], r[3]};
                mma_f16(oacc[2*n2],   pH, b0);
                mma_f16(oacc[2*n2],   pL, b0);
                mma_f16(oacc[2*n2+1], pH, b1);
                mma_f16(oacc[2*n2+1], pL, b1);
            }
        }
    }

    float il1 = 1.0f / l1, il2 = 1.0f / l2;
    size_t t1 = (size_t)(b * SEQ + qbase + w * 16 + r1) * (NH * VDIM) + h * VDIM + cq0;
    size_t t2 = t1 + (size_t)8 * (NH * VDIM);
#pragma unroll
    for (int n = 0; n < 16; n++) {
        store_hilo(g_at_hi, g_at_lo, t1 + n * 8, oacc[n][0] * il1, oacc[n][1] * il1);
        store_hilo(g_at_hi, g_at_lo, t2 + n * 8, oacc[n][2] * il2, oacc[n][3] * il2);
    }
}

// ---------------- Host launcher ----------------
static void launch_split2(const float* src, __half* hi, __half* lo, long long n, cudaStream_t st) {
    int n4 = (int)(n / 4);
    split2_kernel<<<(n4 + 255) / 256, 256, 0, st>>>((const float4*)src, (__half2*)hi, (__half2*)lo, n4);
}
static void launch_split1(const float* src, __half* hi, long long n, cudaStream_t st) {
    int n4 = (int)(n / 4);
    split1_kernel<<<(n4 + 255) / 256, 256, 0, st>>>((const float4*)src, (__half2*)hi, n4);
}

extern "C" void kernel_launch(void* const* d_in, const int* in_sizes, int n_in,
                              void* d_out, int out_size)
{
    const float* x        = (const float*)d_in[0];
    const int*   positions= (const int*)  d_in[1];
    const float* Wq_down  = (const float*)d_in[2];
    const float* Wq_up    = (const float*)d_in[3];
    const float* Wq_rope  = (const float*)d_in[4];
    const float* Wkv_down = (const float*)d_in[5];
    const float* Wk_up    = (const float*)d_in[6];
    const float* Wv_up    = (const float*)d_in[7];
    const float* Wk_rope  = (const float*)d_in[8];
    const float* Wo       = (const float*)d_in[9];
    float* out = (float*)d_out;

    float *p_kr, *p_qr;
    cudaGetSymbolAddress((void**)&p_kr,  g_kr);
    cudaGetSymbolAddress((void**)&p_qr,  g_qr);

    __half *xh,*xl,*cqh,*cql,*ckvh,*ckvl,*ath,*atl,*vch,*Qh,*Ql,*Kh;
    __half *wqd,*wqu,*wqr,*wkvd,*wku,*wvu,*wkr,*wo;
    cudaGetSymbolAddress((void**)&xh,   g_x_hi);   cudaGetSymbolAddress((void**)&xl,   g_x_lo);
    cudaGetSymbolAddress((void**)&cqh,  g_cq_hi);  cudaGetSymbolAddress((void**)&cql,  g_cq_lo);
    cudaGetSymbolAddress((void**)&ckvh, g_ckv_hi); cudaGetSymbolAddress((void**)&ckvl, g_ckv_lo);
    cudaGetSymbolAddress((void**)&ath,  g_at_hi);  cudaGetSymbolAddress((void**)&atl,  g_at_lo);
    cudaGetSymbolAddress((void**)&vch,  g_vchi);
    cudaGetSymbolAddress((void**)&Qh,   g_Qhi);    cudaGetSymbolAddress((void**)&Ql,   g_Qlo);
    cudaGetSymbolAddress((void**)&Kh,   g_Khi);
    cudaGetSymbolAddress((void**)&wqd,  g_wqd);    cudaGetSymbolAddress((void**)&wqu,  g_wqu);
    cudaGetSymbolAddress((void**)&wqr,  g_wqr);    cudaGetSymbolAddress((void**)&wkvd, g_wkvd);
    cudaGetSymbolAddress((void**)&wku,  g_wku);    cudaGetSymbolAddress((void**)&wvu,  g_wvu);
    cudaGetSymbolAddress((void**)&wkr,  g_wkr);    cudaGetSymbolAddress((void**)&wo,   g_wo);

    const int SMEM_128 = 2 * (2 * 128 * 80 + 128 * 80);  // 61440
    const int SMEM_64  = 2 * (2 * 128 * 80 + 64 * 80);   // 51200
    cudaFuncSetAttribute(gemm_f16x2<128,0>, cudaFuncAttributeMaxDynamicSharedMemorySize, SMEM_128);
    cudaFuncSetAttribute(gemm_f16x2<128,1>, cudaFuncAttributeMaxDynamicSharedMemorySize, SMEM_128);
    cudaFuncSetAttribute(gemm_f16x2<128,2>, cudaFuncAttributeMaxDynamicSharedMemorySize, SMEM_128);
    cudaFuncSetAttribute(gemm_f16x2<128,3>, cudaFuncAttributeMaxDynamicSharedMemorySize, SMEM_128);
    cudaFuncSetAttribute(gemm_f16x2<128,4>, cudaFuncAttributeMaxDynamicSharedMemorySize, SMEM_128);
    cudaFuncSetAttribute(gemm_f16x2<64,0>,  cudaFuncAttributeMaxDynamicSharedMemorySize, SMEM_64);
    cudaFuncSetAttribute(flash_mma_kernel,  cudaFuncAttributeMaxDynamicSharedMemorySize, FLASH2_SMEM);

    static cudaStream_t sB = nullptr, sC = nullptr;
    static cudaEvent_t evF = nullptr, evJ = nullptr, evW = nullptr;
    if (sB == nullptr) {
        cudaStreamCreateWithFlags(&sB, cudaStreamNonBlocking);
        cudaStreamCreateWithFlags(&sC, cudaStreamNonBlocking);
        cudaEventCreateWithFlags(&evF, cudaEventDisableTiming);
        cudaEventCreateWithFlags(&evJ, cudaEventDisableTiming);
        cudaEventCreateWithFlags(&evW, cudaEventDisableTiming);
    }
    cudaStream_t s0 = 0;

    // ---- minimal prologue: only what gates the down GEMMs ----
    {
        int n = SEQ * (ROPE_D / 2);
        rope_table_kernel<<<(n + 255) / 256, 256>>>(positions);
    }
    launch_split2(x,       xh,  xl,  (long long)MTOT*DMODEL,   s0);
    launch_split1(Wq_down, wqd,      (long long)Q_RANK*DMODEL, s0);
    launch_split1(Wkv_down,wkvd,     (long long)KV_RANK*DMODEL,s0);

    // ---- fork: KV path on sB, deferred weight splits on sC ----
    cudaEventRecord(evF, s0);
    cudaStreamWaitEvent(sB, evF, 0);
    cudaStreamWaitEvent(sC, evF, 0);

    launch_split1(Wq_up,   wqu, (long long)NH*NOPE*Q_RANK,   sC);
    launch_split1(Wq_rope, wqr, (long long)NH*ROPE_D*Q_RANK, sC);
    launch_split1(Wk_up,   wku, (long long)NH*NOPE*KV_RANK,  sC);
    launch_split1(Wv_up,   wvu, (long long)NH*VDIM*KV_RANK,  sC);
    launch_split1(Wk_rope, wkr, (long long)ROPE_D*DMODEL,    sC);
    launch_split1(Wo,      wo,  (long long)DMODEL*NH*VDIM,   sC);
    cudaEventRecord(evW, sC);

    // KV path (side stream)
    gemm_f16x2<128,1><<<dim3(KV_RANK/128, MTOT/128), 256, SMEM_128, sB>>>(
        xh, xl, wkvd, nullptr, ckvh, ckvl, MTOT, KV_RANK, DMODEL, 1.0f);
    cudaStreamWaitEvent(sB, evW, 0);
    gemm_f16x2<64,0><<<dim3(ROPE_D/64, MTOT/128), 256, SMEM_64, sB>>>(
        xh, xl, wkr, p_kr, nullptr, nullptr, MTOT, ROPE_D, DMODEL, 1.0f);
    gemm_f16x2<128,4><<<dim3(NH*NOPE/128, MTOT/128), 256, SMEM_128, sB>>>(
        ckvh, ckvl, wku, nullptr, Kh, nullptr, MTOT, NH*NOPE, KV_RANK, 1.0f);
    gemm_f16x2<128,3><<<dim3(NH*VDIM/128, MTOT/128), 256, SMEM_128, sB>>>(
        ckvh, ckvl, wvu, nullptr, vch, nullptr, MTOT, NH*VDIM, KV_RANK, 1.0f);
    {
        int total = BSZ * NH * SEQ * ROPE_D;
        pack_k_rope_kernel<<<(total + 255) / 256, 256, 0, sB>>>();
    }

    // Q path (default stream)
    gemm_f16x2<128,1><<<dim3(Q_RANK/128, MTOT/128), 256, SMEM_128>>>(
        xh, xl, wqd, nullptr, cqh, cql, MTOT, Q_RANK, DMODEL, 1.0f);
    cudaStreamWaitEvent(s0, evW, 0);
    gemm_f16x2<128,2><<<dim3(NH*NOPE/128, MTOT/128), 256, SMEM_128>>>(
        cqh, cql, wqu, nullptr, Qh, Ql, MTOT, NH*NOPE, Q_RANK, SCALE);
    gemm_f16x2<128,0><<<dim3(NH*ROPE_D/128, MTOT/128), 256, SMEM_128>>>(
        cqh, cql, wqr, p_qr, nullptr, nullptr, MTOT, NH*ROPE_D, Q_RANK, 1.0f);
    {
        int total = BSZ * NH * SEQ * ROPE_D;
        pack_q_rope_kernel<<<(total + 255) / 256, 256>>>();
    }

    // ---- join ----
    cudaEventRecord(evJ, sB);
    cudaStreamWaitEvent(s0, evJ, 0);

    // Flash attention (BQ=128, 8 warps)
    flash_mma_kernel<<<dim3(SEQ/128, NH, BSZ), 256, FLASH2_SMEM>>>();

    // Output projection
    gemm_f16x2<128,0><<<dim3(DMODEL/128, MTOT/128), 256, SMEM_128>>>(
        ath, atl, wo, out, nullptr, nullptr, MTOT, DMODEL, NH*VDIM, 1.0f);
}

// round 17
// speedup vs baseline: 1.1978x; 1.1978x over previous
#include <cuda_runtime.h>
#include <cuda_fp16.h>
#include <math.h>
#include <stdint.h>

// ---------------- Problem constants ----------------
#define BSZ 2
#define SEQ 2048
#define DMODEL 2048
#define NH 16
#define KV_RANK 512
#define Q_RANK 1536
#define NOPE 128
#define ROPE_D 64
#define VDIM 128
#define QKD 192           // NOPE + ROPE_D
#define MTOT (BSZ*SEQ)    // 4096
#define SCALE 0.07216878364870323f   // 192^-0.5

// ---------------- fp32 scratch ----------------
__device__ float g_kr  [MTOT * ROPE_D];
__device__ float g_qr  [MTOT * NH * ROPE_D];
__device__ float g_cos [SEQ * (ROPE_D/2)];
__device__ float g_sin [SEQ * (ROPE_D/2)];

// ---------------- fp16 scratch ----------------
__device__ __half g_x_hi  [MTOT*DMODEL],    g_x_lo  [MTOT*DMODEL];
__device__ __half g_cq_hi [MTOT*Q_RANK],    g_cq_lo [MTOT*Q_RANK];
__device__ __half g_ckv_hi[MTOT*KV_RANK],   g_ckv_lo[MTOT*KV_RANK];
__device__ __half g_at_hi [MTOT*NH*VDIM];
__device__ __half g_Qhi   [BSZ*NH*SEQ*QKD], g_Qlo   [BSZ*NH*SEQ*QKD];
__device__ __half g_vchi  [MTOT*NH*VDIM];
__device__ __half g_Khi   [BSZ*NH*SEQ*QKD];
__device__ __half g_wqd  [Q_RANK*DMODEL];
__device__ __half g_wqu  [NH*NOPE*Q_RANK];
__device__ __half g_wqr  [NH*ROPE_D*Q_RANK];
__device__ __half g_wkvd [KV_RANK*DMODEL];
__device__ __half g_wku  [NH*NOPE*KV_RANK];
__device__ __half g_wvu  [NH*VDIM*KV_RANK];
__device__ __half g_wkr  [ROPE_D*DMODEL];
__device__ __half g_wo   [DMODEL*NH*VDIM];

// ---------------- helpers ----------------
__device__ __forceinline__ uint32_t smem_u32(const void* p) {
    uint32_t a;
    asm("{ .reg .u64 t; cvta.to.shared.u64 t, %1; cvt.u32.u64 %0, t; }" : "=r"(a) : "l"(p));
    return a;
}
__device__ __forceinline__ void cp16(uint32_t dst, const void* src) {
    asm volatile("cp.async.cg.shared.global [%0], [%1], 16;" :: "r"(dst), "l"(src));
}
__device__ __forceinline__ void ldm4(uint32_t (&r)[4], uint32_t a) {
    asm volatile("ldmatrix.sync.aligned.m8n8.x4.shared.b16 {%0,%1,%2,%3}, [%4];"
                 : "=r"(r[0]), "=r"(r[1]), "=r"(r[2]), "=r"(r[3]) : "r"(a));
}
__device__ __forceinline__ void ldm4t(uint32_t (&r)[4], uint32_t a) {
    asm volatile("ldmatrix.sync.aligned.m8n8.x4.trans.shared.b16 {%0,%1,%2,%3}, [%4];"
                 : "=r"(r[0]), "=r"(r[1]), "=r"(r[2]), "=r"(r[3]) : "r"(a));
}
__device__ __forceinline__ void mma_f16(float (&c)[4], const uint32_t (&a)[4], const uint32_t (&b)[2]) {
    asm volatile("mma.sync.aligned.m16n8k16.row.col.f32.f16.f16.f32 "
                 "{%0,%1,%2,%3}, {%4,%5,%6,%7}, {%8,%9}, {%0,%1,%2,%3};"
                 : "+f"(c[0]), "+f"(c[1]), "+f"(c[2]), "+f"(c[3])
                 : "r"(a[0]), "r"(a[1]), "r"(a[2]), "r"(a[3]), "r"(b[0]), "r"(b[1]));
}
__device__ __forceinline__ void store_hilo(__half* Hi, __half* Lo, size_t off, float a, float b) {
    __half h0 = __float2half_rn(a), h1 = __float2half_rn(b);
    *(__half2*)(Hi + off) = __halves2half2(h0, h1);
    *(__half2*)(Lo + off) = __halves2half2(__float2half_rn(a - __half2float(h0)),
                                           __float2half_rn(b - __half2float(h1)));
}
__device__ __forceinline__ void store_hi(__half* Hi, size_t off, float a, float b) {
    *(__half2*)(Hi + off) = __halves2half2(__float2half_rn(a), __float2half_rn(b));
}

// ---------------- splits ----------------
__global__ void split2_kernel(const float4* __restrict__ src,
                              __half2* __restrict__ hi, __half2* __restrict__ lo, int n4)
{
    int i = blockIdx.x * blockDim.x + threadIdx.x;
    if (i >= n4) return;
    float4 v = src[i];
    __half h0 = __float2half_rn(v.x), h1 = __float2half_rn(v.y);
    __half h2 = __float2half_rn(v.z), h3 = __float2half_rn(v.w);
    hi[2*i]   = __halves2half2(h0, h1);
    hi[2*i+1] = __halves2half2(h2, h3);
    lo[2*i]   = __halves2half2(__float2half_rn(v.x - __half2float(h0)),
                               __float2half_rn(v.y - __half2float(h1)));
    lo[2*i+1] = __halves2half2(__float2half_rn(v.z - __half2float(h2)),
                               __float2half_rn(v.w - __half2float(h3)));
}
__global__ void split1_kernel(const float4* __restrict__ src, __half2* __restrict__ hi, int n4)
{
    int i = blockIdx.x * blockDim.x + threadIdx.x;
    if (i >= n4) return;
    float4 v = src[i];
    hi[2*i]   = __halves2half2(__float2half_rn(v.x), __float2half_rn(v.y));
    hi[2*i+1] = __halves2half2(__float2half_rn(v.z), __float2half_rn(v.w));
}

// ---------------- mma.sync fp16 GEMM: C[M,N] = A[M,K] * B[N,K]^T ----------------
// PASSES=2: A = Ahi + Alo (exact).  PASSES=1: A = Ahi only (fp16-rounded A).
// B = Bhi (fp16-rounded). CTA 128 x TILE_N, 256 threads, BK=32, 2-stage cp.async.
// EPI: 0 fp32 C | 1 hi/lo row-major | 2 hi/lo remap packed [b,h,s,d] (*scl)
//      3 hi-only row-major | 4 hi-only remap packed
template<int TILE_N, int EPI, int PASSES>
__global__ void __launch_bounds__(256) gemm_f16x2(
    const __half* __restrict__ Ahi, const __half* __restrict__ Alo,
    const __half* __restrict__ Bhi,
    float* __restrict__ C,
    __half* __restrict__ Chi, __half* __restrict__ Clo,
    int M, int N, int K, float scl)
{
    constexpr int BK = 32;
    constexpr int ASTR = 40;
    constexpr int ABYTES = 128 * ASTR * 2;
    constexpr int BBYTES = TILE_N * ASTR * 2;
    constexpr int STAGE  = 2 * ABYTES + BBYTES;
    constexpr int WN = TILE_N / 4;
    constexpr int NT = WN / 8;

    extern __shared__ char sm_raw[];
    const uint32_t s0 = smem_u32(sm_raw);

    const int tid  = threadIdx.x;
    const int lane = tid & 31;
    const int warp = tid >> 5;
    const int wm0  = (warp & 1) * 64;
    const int wn0  = (warp >> 1) * WN;
    const int mBase = blockIdx.y * 128;
    const int nBase = blockIdx.x * TILE_N;

    float acc[4][NT][4];
#pragma unroll
    for (int i = 0; i < 4; i++)
#pragma unroll
        for (int j = 0; j < NT; j++)
#pragma unroll
            for (int q = 0; q < 4; q++) acc[i][j][q] = 0.0f;

    auto load = [&](int c, int s) {
        uint32_t base = s0 + s * STAGE;
        int k0 = c * BK;
#pragma unroll
        for (int i = 0; i < 2; i++) {
            int idx = tid + i * 256;
            int row = idx >> 2, c4 = idx & 3;
            uint32_t d = base + row * (ASTR * 2) + c4 * 16;
            const size_t goff = (size_t)(mBase + row) * K + k0 + c4 * 8;
            cp16(d, Ahi + goff);
            if (PASSES == 2) cp16(d + ABYTES, Alo + goff);
        }
#pragma unroll
        for (int i = 0; i < TILE_N / 64; i++) {
            int idx = tid + i * 256;
            int row = idx >> 2, c4 = idx & 3;
            uint32_t d = base + 2 * ABYTES + row * (ASTR * 2) + c4 * 16;
            const size_t goff = (size_t)(nBase + row) * K + k0 + c4 * 8;
            cp16(d, Bhi + goff);
        }
        asm volatile("cp.async.commit_group;" ::: "memory");
    };

    const int nch = K / BK;
    load(0, 0);

    for (int c = 0; c < nch; c++) {
        const int s = c & 1;
        if (c + 1 < nch) {
            load(c + 1, s ^ 1);
            asm volatile("cp.async.wait_group 1;" ::: "memory");
        } else {
            asm volatile("cp.async.wait_group 0;" ::: "memory");
        }
        __syncthreads();

        const uint32_t aB = s0 + s * STAGE;
        const uint32_t bB = aB + 2 * ABYTES;
#pragma unroll
        for (int ks = 0; ks < 2; ks++) {
            uint32_t aH[4][4], aL[4][4];
#pragma unroll
            for (int i = 0; i < 4; i++) {
                int row = wm0 + i * 16 + (lane & 15);
                int kc  = ks * 16 + (lane >> 4) * 8;
                uint32_t ad = aB + row * (ASTR * 2) + kc * 2;
                ldm4(aH[i], ad);
                if (PASSES == 2) ldm4(aL[i], ad + ABYTES);
            }
            uint32_t bF[NT][2];
#pragma unroll
            for (int j2 = 0; j2 < NT / 2; j2++) {
                int nrow = wn0 + j2 * 16 + ((lane >> 4) << 3) + (lane & 7);
                int kc   = ks * 16 + ((lane >> 3) & 1) * 8;
                uint32_t bd = bB + nrow * (ASTR * 2) + kc * 2;
                uint32_t r[4];
                ldm4(r, bd);
                bF[2*j2][0] = r[0]; bF[2*j2][1] = r[1];
                bF[2*j2+1][0] = r[2]; bF[2*j2+1][1] = r[3];
            }
#pragma unroll
            for (int i = 0; i < 4; i++)
#pragma unroll
                for (int j = 0; j < NT; j++) {
                    mma_f16(acc[i][j], aH[i], bF[j]);
                    if (PASSES == 2) mma_f16(acc[i][j], aL[i], bF[j]);
                }
        }
        __syncthreads();
    }

#pragma unroll
    for (int i = 0; i < 4; i++)
#pragma unroll
        for (int j = 0; j < NT; j++) {
            int row = mBase + wm0 + i * 16 + (lane >> 2);
            int col = nBase + wn0 + j * 8 + (lane & 3) * 2;
            if (EPI == 0) {
                *(float2*)(C + (size_t)row * N + col)       = make_float2(acc[i][j][0], acc[i][j][1]);
                *(float2*)(C + (size_t)(row + 8) * N + col) = make_float2(acc[i][j][2], acc[i][j][3]);
            } else if (EPI == 1) {
                store_hilo(Chi, Clo, (size_t)row * N + col,       acc[i][j][0], acc[i][j][1]);
                store_hilo(Chi, Clo, (size_t)(row + 8) * N + col, acc[i][j][2], acc[i][j][3]);
            } else if (EPI == 3) {
                store_hi(Chi, (size_t)row * N + col,       acc[i][j][0], acc[i][j][1]);
                store_hi(Chi, (size_t)(row + 8) * N + col, acc[i][j][2], acc[i][j][3]);
            } else {
                int bb = row >> 11, ss = row & (SEQ - 1);
                int hh = col >> 7,  dd = col & 127;
                size_t o1 = (((size_t)(bb * NH + hh)) * SEQ + ss) * QKD + dd;
                if (EPI == 2) {
                    store_hilo(Chi, Clo, o1,           acc[i][j][0] * scl, acc[i][j][1] * scl);
                    store_hilo(Chi, Clo, o1 + 8 * QKD, acc[i][j][2] * scl, acc[i][j][3] * scl);
                } else {   // EPI == 4
                    store_hi(Chi, o1,           acc[i][j][0], acc[i][j][1]);
                    store_hi(Chi, o1 + 8 * QKD, acc[i][j][2], acc[i][j][3]);
                }
            }
        }
}

// ---------------- RoPE cos/sin table ----------------
__global__ void rope_table_kernel(const int* __restrict__ positions)
{
    int idx = blockIdx.x * blockDim.x + threadIdx.x;
    if (idx >= SEQ * (ROPE_D/2)) return;
    int s = idx / (ROPE_D/2);
    int i = idx % (ROPE_D/2);
    float pos = (float)positions[s];
    float inv = expf(-logf(10000.0f) * (float)i / (float)(ROPE_D/2));
    float ang = pos * inv;
    g_cos[idx] = cosf(ang);
    g_sin[idx] = sinf(ang);
}

// ---------------- Pack Q rope dims -> [b,h,s,128+d] hi/lo ----------------
__global__ void pack_q_rope_kernel()
{
    int idx = blockIdx.x * blockDim.x + threadIdx.x;
    const int total = BSZ * NH * SEQ * ROPE_D;
    if (idx >= total) return;
    int d = idx & (ROPE_D - 1);
    int s = (idx >> 6) & (SEQ - 1);
    int h = (idx >> 17) & (NH - 1);
    int b = idx >> 21;
    int row = b * SEQ + s;
    int i = d & 31;
    float c = g_cos[s * 32 + i];
    float sn = g_sin[s * 32 + i];
    float t1 = g_qr[(size_t)row * (NH * ROPE_D) + h * ROPE_D + i];
    float t2 = g_qr[(size_t)row * (NH * ROPE_D) + h * ROPE_D + i + 32];
    float val = ((d < 32) ? (t1 * c - t2 * sn) : (t2 * c + t1 * sn)) * SCALE;
    size_t o = (((size_t)(b * NH + h)) * SEQ + s) * QKD + NOPE + d;
    __half hh = __float2half_rn(val);
    g_Qhi[o] = hh;
    g_Qlo[o] = __float2half_rn(val - __half2float(hh));
}

// ---------------- Pack K rope dims (shared head) -> hi only ----------------
__global__ void pack_k_rope_kernel()
{
    int idx = blockIdx.x * blockDim.x + threadIdx.x;
    const int total = BSZ * NH * SEQ * ROPE_D;
    if (idx >= total) return;
    int d = idx & (ROPE_D - 1);
    int s = (idx >> 6) & (SEQ - 1);
    int h = (idx >> 17) & (NH - 1);
    int b = idx >> 21;
    int row = b * SEQ + s;
    int i = d & 31;
    float c = g_cos[s * 32 + i];
    float sn = g_sin[s * 32 + i];
    float t1 = g_kr[(size_t)row * ROPE_D + i];
    float t2 = g_kr[(size_t)row * ROPE_D + i + 32];
    float val = (d < 32) ? (t1 * c - t2 * sn) : (t2 * c + t1 * sn);
    size_t o = (((size_t)(b * NH + h)) * SEQ + s) * QKD + NOPE + d;
    g_Khi[o] = __float2half_rn(val);
}

// ---------------- Flash attention (mma.sync fp16x2, causal, BQ=64, 128 thr) ----------------
// smem: Qhi 64x400, Qlo 64x400, Khi 64x400, Vhi 64x272, Phi 64x144, Plo 64x144
#define QHI_OFF 0
#define QLO_OFF 25600
#define KHI_OFF 51200
#define VHI_OFF 76800
#define PHI_OFF 94208
#define PLO_OFF 103424
#define FLASH2_SMEM 112640

__global__ void __launch_bounds__(128) flash_mma_kernel()
{
    extern __shared__ char smc[];
    const uint32_t s0 = smem_u32(smc);
    const int tid = threadIdx.x, lane = tid & 31, w = tid >> 5;
    const int qt = gridDim.x - 1 - blockIdx.x;   // big tiles first
    const int h = blockIdx.y, b = blockIdx.z;
    const int qbase = qt * 64;
    const size_t qkB = ((size_t)(b * NH + h) * SEQ) * QKD;
    const int r1 = lane >> 2;
    const int cq0 = (lane & 3) * 2;

#pragma unroll
    for (int i = 0; i < 12; i++) {
        int idx = tid + i * 128;
        int row = idx / 24, c8 = idx % 24;
        size_t g = qkB + (size_t)(qbase + row) * QKD + c8 * 8;
        *(uint4*)(smc + QHI_OFF + row * 400 + c8 * 16) = *(const uint4*)(g_Qhi + g);
        *(uint4*)(smc + QLO_OFF + row * 400 + c8 * 16) = *(const uint4*)(g_Qlo + g);
    }

    float oacc[16][4];
#pragma unroll
    for (int n = 0; n < 16; n++)
#pragma unroll
        for (int q = 0; q < 4; q++) oacc[n][q] = 0.0f;
    float m1 = -INFINITY, m2 = -INFINITY, l1 = 0.0f, l2 = 0.0f;

    for (int kt = 0; kt <= qt; kt++) {
        const int kbase = kt * 64;
        __syncthreads();
#pragma unroll
        for (int i = 0; i < 12; i++) {
            int idx = tid + i * 128;
            int row = idx / 24, c8 = idx % 24;
            size_t g = qkB + (size_t)(kbase + row) * QKD + c8 * 8;
            *(uint4*)(smc + KHI_OFF + row * 400 + c8 * 16) = *(const uint4*)(g_Khi + g);
        }
#pragma unroll
        for (int i = 0; i < 8; i++) {
            int idx = tid + i * 128;
            int row = idx / 16, c8 = idx % 16;
            size_t g = (size_t)(b * SEQ + kbase + row) * (NH * VDIM) + h * VDIM + c8 * 8;
            *(uint4*)(smc + VHI_OFF + row * 272 + c8 * 16) = *(const uint4*)(g_vchi + g);
        }
        __syncthreads();

        float sacc[8][4];
#pragma unroll
        for (int j = 0; j < 8; j++)
#pragma unroll
            for (int q = 0; q < 4; q++) sacc[j][q] = 0.0f;

#pragma unroll
        for (int ks = 0; ks < 12; ks++) {
            uint32_t aH[4], aL[4];
            uint32_t aaddr = s0 + QHI_OFF + (w * 16 + (lane & 15)) * 400
                           + (ks * 16 + (lane >> 4) * 8) * 2;
            ldm4(aH, aaddr);
            ldm4(aL, aaddr + 25600);
#pragma unroll
            for (int j2 = 0; j2 < 4; j2++) {
                uint32_t baddr = s0 + KHI_OFF
                               + (j2 * 16 + ((lane >> 4) << 3) + (lane & 7)) * 400
                               + (ks * 16 + ((lane >> 3) & 1) * 8) * 2;
                uint32_t r[4];
                ldm4(r, baddr);
                uint32_t b0[2] = {r[0], r[1]}, b1[2] = {r[2], r[3]};
                mma_f16(sacc[2*j2],   aH, b0);
                mma_f16(sacc[2*j2],   aL, b0);
                mma_f16(sacc[2*j2+1], aH, b1);
                mma_f16(sacc[2*j2+1], aL, b1);
            }
        }

        if (kt == qt) {
            int q1 = qbase + w * 16 + r1;
#pragma unroll
            for (int j = 0; j < 8; j++) {
                int kv = kbase + j * 8 + cq0;
                if (kv     > q1)     sacc[j][0] = -1e30f;
                if (kv + 1 > q1)     sacc[j][1] = -1e30f;
                if (kv     > q1 + 8) sacc[j][2] = -1e30f;
                if (kv + 1 > q1 + 8) sacc[j][3] = -1e30f;
            }
        }

        float mx1 = -1e30f, mx2 = -1e30f;
#pragma unroll
        for (int j = 0; j < 8; j++) {
            mx1 = fmaxf(mx1, fmaxf(sacc[j][0], sacc[j][1]));
            mx2 = fmaxf(mx2, fmaxf(sacc[j][2], sacc[j][3]));
        }
        mx1 = fmaxf(mx1, __shfl_xor_sync(0xFFFFFFFFu, mx1, 1));
        mx1 = fmaxf(mx1, __shfl_xor_sync(0xFFFFFFFFu, mx1, 2));
        mx2 = fmaxf(mx2, __shfl_xor_sync(0xFFFFFFFFu, mx2, 1));
        mx2 = fmaxf(mx2, __shfl_xor_sync(0xFFFFFFFFu, mx2, 2));
        float mn1 = fmaxf(m1, mx1), mn2 = fmaxf(m2, mx2);
        float a1 = expf(m1 - mn1), a2 = expf(m2 - mn2);
        float su1 = 0.0f, su2 = 0.0f;
#pragma unroll
        for (int j = 0; j < 8; j++) {
            sacc[j][0] = expf(sacc[j][0] - mn1);
            sacc[j][1] = expf(sacc[j][1] - mn1);
            sacc[j][2] = expf(sacc[j][2] - mn2);
            sacc[j][3] = expf(sacc[j][3] - mn2);
            su1 += sacc[j][0] + sacc[j][1];
            su2 += sacc[j][2] + sacc[j][3];
        }
        su1 += __shfl_xor_sync(0xFFFFFFFFu, su1, 1);
        su1 += __shfl_xor_sync(0xFFFFFFFFu, su1, 2);
        su2 += __shfl_xor_sync(0xFFFFFFFFu, su2, 1);
        su2 += __shfl_xor_sync(0xFFFFFFFFu, su2, 2);
        m1 = mn1; m2 = mn2;
        l1 = l1 * a1 + su1;
        l2 = l2 * a2 + su2;

        // P hi/lo to smem (stride 144B)
#pragma unroll
        for (int j = 0; j < 8; j++) {
            float p0 = sacc[j][0], p1 = sacc[j][1];
            __half h0 = __float2half_rn(p0), h1 = __float2half_rn(p1);
            int off = (w * 16 + r1) * 144 + (j * 8 + cq0) * 2;
            *(__half2*)(smc + PHI_OFF + off) = __halves2half2(h0, h1);
            *(__half2*)(smc + PLO_OFF + off) =
                __halves2half2(__float2half_rn(p0 - __half2float(h0)),
                               __float2half_rn(p1 - __half2float(h1)));
            float p2 = sacc[j][2], p3 = sacc[j][3];
            __half h2 = __float2half_rn(p2), h3 = __float2half_rn(p3);
            int off2 = (w * 16 + r1 + 8) * 144 + (j * 8 + cq0) * 2;
            *(__half2*)(smc + PHI_OFF + off2) = __halves2half2(h2, h3);
            *(__half2*)(smc + PLO_OFF + off2) =
                __halves2half2(__float2half_rn(p2 - __half2float(h2)),
                               __float2half_rn(p3 - __half2float(h3)));
        }
        __syncwarp();

#pragma unroll
        for (int n = 0; n < 16; n++) {
            oacc[n][0] *= a1; oacc[n][1] *= a1;
            oacc[n][2] *= a2; oacc[n][3] *= a2;
        }

#pragma unroll
        for (int ks = 0; ks < 4; ks++) {
            uint32_t pH[4], pL[4];
            uint32_t paddr = s0 + PHI_OFF + (w * 16 + (lane & 15)) * 144
                           + (ks * 16 + (lane >> 4) * 8) * 2;
            ldm4(pH, paddr);
            ldm4(pL, paddr + 9216);
#pragma unroll
            for (int n2 = 0; n2 < 8; n2++) {
                uint32_t vaddr = s0 + VHI_OFF + (ks * 16 + (lane & 15)) * 272
                               + (n2 * 16 + ((lane >> 4) << 3)) * 2;
                uint32_t r[4];
                ldm4t(r, vaddr);
                uint32_t b0[2] = {r[0], r[1]}, b1[2] = {r[2], r[3]};
                mma_f16(oacc[2*n2],   pH, b0);
                mma_f16(oacc[2*n2],   pL, b0);
                mma_f16(oacc[2*n2+1], pH, b1);
                mma_f16(oacc[2*n2+1], pL, b1);
            }
        }
    }

    // epilogue: hi-only (Wo GEMM is single-pass now)
    float il1 = 1.0f / l1, il2 = 1.0f / l2;
    size_t t1 = (size_t)(b * SEQ + qbase + w * 16 + r1) * (NH * VDIM) + h * VDIM + cq0;
    size_t t2 = t1 + (size_t)8 * (NH * VDIM);
#pragma unroll
    for (int n = 0; n < 16; n++) {
        store_hi(g_at_hi, t1 + n * 8, oacc[n][0] * il1, oacc[n][1] * il1);
        store_hi(g_at_hi, t2 + n * 8, oacc[n][2] * il2, oacc[n][3] * il2);
    }
}

// ---------------- Host launcher ----------------
static void launch_split2(const float* src, __half* hi, __half* lo, long long n, cudaStream_t st) {
    int n4 = (int)(n / 4);
    split2_kernel<<<(n4 + 255) / 256, 256, 0, st>>>((const float4*)src, (__half2*)hi, (__half2*)lo, n4);
}
static void launch_split1(const float* src, __half* hi, long long n, cudaStream_t st) {
    int n4 = (int)(n / 4);
    split1_kernel<<<(n4 + 255) / 256, 256, 0, st>>>((const float4*)src, (__half2*)hi, n4);
}

extern "C" void kernel_launch(void* const* d_in, const int* in_sizes, int n_in,
                              void* d_out, int out_size)
{
    const float* x        = (const float*)d_in[0];
    const int*   positions= (const int*)  d_in[1];
    const float* Wq_down  = (const float*)d_in[2];
    const float* Wq_up    = (const float*)d_in[3];
    const float* Wq_rope  = (const float*)d_in[4];
    const float* Wkv_down = (const float*)d_in[5];
    const float* Wk_up    = (const float*)d_in[6];
    const float* Wv_up    = (const float*)d_in[7];
    const float* Wk_rope  = (const float*)d_in[8];
    const float* Wo       = (const float*)d_in[9];
    float* out = (float*)d_out;

    float *p_kr, *p_qr;
    cudaGetSymbolAddress((void**)&p_kr,  g_kr);
    cudaGetSymbolAddress((void**)&p_qr,  g_qr);

    __half *xh,*xl,*cqh,*cql,*ckvh,*ckvl,*ath,*vch,*Qh,*Ql,*Kh;
    __half *wqd,*wqu,*wqr,*wkvd,*wku,*wvu,*wkr,*wo;
    cudaGetSymbolAddress((void**)&xh,   g_x_hi);   cudaGetSymbolAddress((void**)&xl,   g_x_lo);
    cudaGetSymbolAddress((void**)&cqh,  g_cq_hi);  cudaGetSymbolAddress((void**)&cql,  g_cq_lo);
    cudaGetSymbolAddress((void**)&ckvh, g_ckv_hi); cudaGetSymbolAddress((void**)&ckvl, g_ckv_lo);
    cudaGetSymbolAddress((void**)&ath,  g_at_hi);
    cudaGetSymbolAddress((void**)&vch,  g_vchi);
    cudaGetSymbolAddress((void**)&Qh,   g_Qhi);    cudaGetSymbolAddress((void**)&Ql,   g_Qlo);
    cudaGetSymbolAddress((void**)&Kh,   g_Khi);
    cudaGetSymbolAddress((void**)&wqd,  g_wqd);    cudaGetSymbolAddress((void**)&wqu,  g_wqu);
    cudaGetSymbolAddress((void**)&wqr,  g_wqr);    cudaGetSymbolAddress((void**)&wkvd, g_wkvd);
    cudaGetSymbolAddress((void**)&wku,  g_wku);    cudaGetSymbolAddress((void**)&wvu,  g_wvu);
    cudaGetSymbolAddress((void**)&wkr,  g_wkr);    cudaGetSymbolAddress((void**)&wo,   g_wo);

    const int SMEM_128 = 2 * (2 * 128 * 80 + 128 * 80);  // 61440
    const int SMEM_64  = 2 * (2 * 128 * 80 + 64 * 80);   // 51200
    cudaFuncSetAttribute(gemm_f16x2<128,0,2>, cudaFuncAttributeMaxDynamicSharedMemorySize, SMEM_128);
    cudaFuncSetAttribute(gemm_f16x2<128,1,2>, cudaFuncAttributeMaxDynamicSharedMemorySize, SMEM_128);
    cudaFuncSetAttribute(gemm_f16x2<128,2,2>, cudaFuncAttributeMaxDynamicSharedMemorySize, SMEM_128);
    cudaFuncSetAttribute(gemm_f16x2<128,0,1>, cudaFuncAttributeMaxDynamicSharedMemorySize, SMEM_128);
    cudaFuncSetAttribute(gemm_f16x2<128,3,1>, cudaFuncAttributeMaxDynamicSharedMemorySize, SMEM_128);
    cudaFuncSetAttribute(gemm_f16x2<128,4,1>, cudaFuncAttributeMaxDynamicSharedMemorySize, SMEM_128);
    cudaFuncSetAttribute(gemm_f16x2<64,0,2>,  cudaFuncAttributeMaxDynamicSharedMemorySize, SMEM_64);
    cudaFuncSetAttribute(flash_mma_kernel,    cudaFuncAttributeMaxDynamicSharedMemorySize, FLASH2_SMEM);

    static cudaStream_t sB = nullptr, sC = nullptr;
    static cudaEvent_t evF = nullptr, evJ = nullptr, evW = nullptr;
    if (sB == nullptr) {
        cudaStreamCreateWithFlags(&sB, cudaStreamNonBlocking);
        cudaStreamCreateWithFlags(&sC, cudaStreamNonBlocking);
        cudaEventCreateWithFlags(&evF, cudaEventDisableTiming);
        cudaEventCreateWithFlags(&evJ, cudaEventDisableTiming);
        cudaEventCreateWithFlags(&evW, cudaEventDisableTiming);
    }
    cudaStream_t s0 = 0;

    // ---- minimal prologue: only what gates the down GEMMs ----
    {
        int n = SEQ * (ROPE_D / 2);
        rope_table_kernel<<<(n + 255) / 256, 256>>>(positions);
    }
    launch_split2(x,       xh,  xl,  (long long)MTOT*DMODEL,   s0);
    launch_split1(Wq_down, wqd,      (long long)Q_RANK*DMODEL, s0);
    launch_split1(Wkv_down,wkvd,     (long long)KV_RANK*DMODEL,s0);

    // ---- fork: KV path on sB, deferred weight splits on sC ----
    cudaEventRecord(evF, s0);
    cudaStreamWaitEvent(sB, evF, 0);
    cudaStreamWaitEvent(sC, evF, 0);

    launch_split1(Wq_up,   wqu, (long long)NH*NOPE*Q_RANK,   sC);
    launch_split1(Wq_rope, wqr, (long long)NH*ROPE_D*Q_RANK, sC);
    launch_split1(Wk_up,   wku, (long long)NH*NOPE*KV_RANK,  sC);
    launch_split1(Wv_up,   wvu, (long long)NH*VDIM*KV_RANK,  sC);
    launch_split1(Wk_rope, wkr, (long long)ROPE_D*DMODEL,    sC);
    launch_split1(Wo,      wo,  (long long)DMODEL*NH*VDIM,   sC);
    cudaEventRecord(evW, sC);

    // KV path (side stream)
    gemm_f16x2<128,1,2><<<dim3(KV_RANK/128, MTOT/128), 256, SMEM_128, sB>>>(
        xh, xl, wkvd, nullptr, ckvh, ckvl, MTOT, KV_RANK, DMODEL, 1.0f);
    cudaStreamWaitEvent(sB, evW, 0);
    gemm_f16x2<64,0,2><<<dim3(ROPE_D/64, MTOT/128), 256, SMEM_64, sB>>>(
        xh, xl, wkr, p_kr, nullptr, nullptr, MTOT, ROPE_D, DMODEL, 1.0f);
    gemm_f16x2<128,4,1><<<dim3(NH*NOPE/128, MTOT/128), 256, SMEM_128, sB>>>(
        ckvh, nullptr, wku, nullptr, Kh, nullptr, MTOT, NH*NOPE, KV_RANK, 1.0f);
    gemm_f16x2<128,3,1><<<dim3(NH*VDIM/128, MTOT/128), 256, SMEM_128, sB>>>(
        ckvh, nullptr, wvu, nullptr, vch, nullptr, MTOT, NH*VDIM, KV_RANK, 1.0f);
    {
        int total = BSZ * NH * SEQ * ROPE_D;
        pack_k_rope_kernel<<<(total + 255) / 256, 256, 0, sB>>>();
    }

    // Q path (default stream)
    gemm_f16x2<128,1,2><<<dim3(Q_RANK/128, MTOT/128), 256, SMEM_128>>>(
        xh, xl, wqd, nullptr, cqh, cql, MTOT, Q_RANK, DMODEL, 1.0f);
    cudaStreamWaitEvent(s0, evW, 0);
    gemm_f16x2<128,2,2><<<dim3(NH*NOPE/128, MTOT/128), 256, SMEM_128>>>(
        cqh, cql, wqu, nullptr, Qh, Ql, MTOT, NH*NOPE, Q_RANK, SCALE);
    gemm_f16x2<128,0,1><<<dim3(NH*ROPE_D/128, MTOT/128), 256, SMEM_128>>>(
        cqh, nullptr, wqr, p_qr, nullptr, nullptr, MTOT, NH*ROPE_D, Q_RANK, 1.0f);
    {
        int total = BSZ * NH * SEQ * ROPE_D;
        pack_q_rope_kernel<<<(total + 255) / 256, 256>>>();
    }

    // ---- join ----
    cudaEventRecord(evJ, sB);
    cudaStreamWaitEvent(s0, evJ, 0);

    // Flash attention (BQ=64, 128 thr — R15 geometry)
    flash_mma_kernel<<<dim3(SEQ/64, NH, BSZ), 128, FLASH2_SMEM>>>();

    // Output projection (single-pass A)
    gemm_f16x2<128,0,1><<<dim3(DMODEL/128, MTOT/128), 256, SMEM_128>>>(
        ath, nullptr, wo, out, nullptr, nullptr, MTOT, DMODEL, NH*VDIM, 1.0f);
}